// round 15
// baseline (speedup 1.0000x reference)
#include <cuda_runtime.h>
#include <math_constants.h>
#include <cstdint>

#define NB   64
#define LL   577
#define DD   512
#define EE   1024
#define HH   512
#define KSEL 288
#define MM   (NB * KSEL)        // 18432 rows
#define NPART 576

// fixed-point scales: a_q = round(a*S) in [-32512, 32512]; split into hi*256+lo
#define S_W  (32512.0f * 22.62741699796952f)  // weights bounded by 1/sqrt(512)
#define S_AF 32512.0f                          // feats: |a| <= 1 (unit-norm rows)
#define S_AH (32512.0f / 6.0f)                 // relu_bn_h: amax 6 (max ~5.2 over 9.4M N(0,1))

// ---------------- scratch (static device globals; no allocation) -------------
__device__ __align__(16) int8_t g_fhi[(size_t)MM * 512];
__device__ __align__(16) int8_t g_flo[(size_t)MM * 512];
__device__ __align__(16) int8_t g_hhi[(size_t)MM * 512];
__device__ __align__(16) int8_t g_hlo[(size_t)MM * 512];
__device__ __align__(16) float  g_h[(size_t)MM * 512];
__device__ __align__(16) float  g_local[(size_t)MM * 1024];
__device__ __align__(16) int8_t g_w0hi[512 * 512];
__device__ __align__(16) int8_t g_w0lo[512 * 512];
__device__ __align__(16) int8_t g_w1hi[1024 * 512];
__device__ __align__(16) int8_t g_w1lo[1024 * 512];
__device__ __align__(16) int8_t g_fchi[1024 * 512];
__device__ __align__(16) int8_t g_fclo[1024 * 512];
__device__ __align__(16) float g_bias2[1024];
__device__ __align__(16) float g_psum[NPART * 512];
__device__ __align__(16) float g_psq [NPART * 512];
__device__ __align__(16) float g_scale[512];
__device__ __align__(16) float g_shift[512];
__device__ int g_sel[NB * KSEL];

// ---------------- helpers ----------------------------------------------------
__device__ __forceinline__ uint32_t smem_u32(const void* p) {
    uint32_t a;
    asm("{ .reg .u64 t; cvta.to.shared.u64 t, %1; cvt.u32.u64 %0, t; }" : "=r"(a) : "l"(p));
    return a;
}
__device__ __forceinline__ void cp_async16(uint32_t saddr, const void* gaddr) {
    asm volatile("cp.async.cg.shared.global [%0], [%1], 16;" :: "r"(saddr), "l"(gaddr));
}
#define CP_COMMIT() asm volatile("cp.async.commit_group;" ::: "memory")
#define CP_WAIT1()  asm volatile("cp.async.wait_group 1;" ::: "memory")

__device__ __forceinline__ void ldsm_x4(uint32_t& r0, uint32_t& r1, uint32_t& r2, uint32_t& r3,
                                        uint32_t addr) {
    asm volatile("ldmatrix.sync.aligned.m8n8.x4.shared.b16 {%0,%1,%2,%3}, [%4];"
                 : "=r"(r0), "=r"(r1), "=r"(r2), "=r"(r3) : "r"(addr));
}
__device__ __forceinline__ void mma_s8(int& d0, int& d1, int& d2, int& d3,
                                       uint32_t a0, uint32_t a1, uint32_t a2, uint32_t a3,
                                       uint32_t b0, uint32_t b1) {
    asm volatile("mma.sync.aligned.m16n8k32.row.col.s32.s8.s8.s32 "
                 "{%0,%1,%2,%3}, {%4,%5,%6,%7}, {%8,%9}, {%0,%1,%2,%3};"
                 : "+r"(d0), "+r"(d1), "+r"(d2), "+r"(d3)
                 : "r"(a0), "r"(a1), "r"(a2), "r"(a3), "r"(b0), "r"(b1));
}
__device__ __forceinline__ void atomicMaxFloat(float* addr, float val) {
    if (__float_as_int(val) >= 0) atomicMax((int*)addr, __float_as_int(val));
    else atomicMin((unsigned int*)addr, __float_as_uint(val));
}
__device__ __forceinline__ void quant16(float a, float S, int8_t& hi, int8_t& lo) {
    int q = __float2int_rn(a * S);
    q = max(-32512, min(32512, q));
    const int h = (q + 128) >> 8;          // round-nearest, h in [-127,127]
    hi = (int8_t)h;
    lo = (int8_t)(q - (h << 8));           // in [-128,127]
}

// ---------------- small kernels ----------------------------------------------
__global__ void init_out_kernel(float* __restrict__ out) {
    int i = blockIdx.x * blockDim.x + threadIdx.x;
    if (i < NB * EE) out[i] = -CUDART_INF_F;
}

__global__ void topk_kernel(const float* __restrict__ atten) {
    __shared__ float s[LL];
    const int b = blockIdx.x;
    const float* __restrict__ row = atten + (size_t)b * LL * LL;
    for (int i = threadIdx.x; i < LL; i += blockDim.x)
        s[i] = (i == 0) ? -1.0f : row[i];
    __syncthreads();
    for (int i = threadIdx.x; i < LL; i += blockDim.x) {
        const float si = s[i];
        int rank = 0;
        #pragma unroll 4
        for (int j = 0; j < LL; ++j) {
            const float sj = s[j];
            rank += (sj > si) || (sj == si && j < i);
        }
        if (rank < KSEL) g_sel[b * KSEL + rank] = i;
    }
}

// gather + L2-norm + int16-fixedpoint quantize feats (|a| <= 1 guaranteed)
__global__ void gather_quant_kernel(const float* __restrict__ basef) {
    const int t = blockIdx.x, b = blockIdx.y;
    const int n = b * KSEL + t;
    const int tok = g_sel[n];
    const float4* src = (const float4*)(basef + ((size_t)b * LL + tok) * DD);
    const float4 v = src[threadIdx.x];
    float ss = v.x * v.x + v.y * v.y + v.z * v.z + v.w * v.w;
    #pragma unroll
    for (int off = 16; off > 0; off >>= 1)
        ss += __shfl_xor_sync(0xffffffffu, ss, off);
    __shared__ float wsum[4];
    const int lane = threadIdx.x & 31, wid = threadIdx.x >> 5;
    if (lane == 0) wsum[wid] = ss;
    __syncthreads();
    const float tot = wsum[0] + wsum[1] + wsum[2] + wsum[3];
    const float inv = 1.0f / (sqrtf(tot) + 1e-8f);
    int8_t hi[4], lo[4];
    quant16(v.x * inv, S_AF, hi[0], lo[0]);
    quant16(v.y * inv, S_AF, hi[1], lo[1]);
    quant16(v.z * inv, S_AF, hi[2], lo[2]);
    quant16(v.w * inv, S_AF, hi[3], lo[3]);
    const size_t off = (size_t)n * 512 + threadIdx.x * 4;
    *(uint32_t*)(g_fhi + off) = *(uint32_t*)hi;
    *(uint32_t*)(g_flo + off) = *(uint32_t*)lo;
}

__global__ void quant_w_kernel(const float* __restrict__ w, int8_t* __restrict__ whi,
                               int8_t* __restrict__ wlo, int count) {
    const int i = blockIdx.x * blockDim.x + threadIdx.x;
    if (i >= count) return;
    int8_t hi, lo;
    quant16(w[i], S_W, hi, lo);
    whi[i] = hi;
    wlo[i] = lo;
}
__global__ void bias2_kernel(const float* __restrict__ b1, const float* __restrict__ bfc) {
    const int i = blockIdx.x * blockDim.x + threadIdx.x;
    if (i < 1024) g_bias2[i] = b1[i] + bfc[i];
}

// ---------------- IMMA GEMM: int8 split fixed-point, 3 passes -----------------
// C = (65536*acc_hh + 256*acc_mid) * invScale (+ bias / + partial, + max)
// acc_hh += Ahi*Bhi;  acc_mid += Ahi*Blo + Alo*Bhi   (lo*lo dropped, ~2^-16)
// CTA tile 128x128, K-tile 64 int8 (64B rows -> same swizzle/ldsm as R8 bf16),
// 2 k32 MMA steps per ktile, 3-stage cp.async, 8 warps (2M x 4N), warp 64x32.
// m16n8k32 s8 fragment byte-layout == f16 m16n8k16 k-half pairs -> proven
// ldmatrix addressing reused verbatim.
// EPI 0: out = v + bias[col]
// EPI 2: v += partial[row*ldo+col]; fused per-batch max into out (init -inf)
#define STAGE_BYTES 32768   // Ahi 8K | Alo 8K | Bhi 8K | Blo 8K
#define SMEM_DYN (3 * STAGE_BYTES + 128)
extern __shared__ char dynsm[];

template<int EPI>
__global__ void __launch_bounds__(256, 1) imma_gemm_kernel(
    const int8_t* __restrict__ aHi, const int8_t* __restrict__ aLo, int lda,
    const int8_t* __restrict__ bHi, const int8_t* __restrict__ bLo, int ldb,
    const float* __restrict__ bias, const float* __restrict__ partial,
    float invS, float* __restrict__ out, int ldo, int KT) {
    const int tid  = threadIdx.x;
    const int lane = tid & 31;
    const int wid  = tid >> 5;
    const int warp_m = wid & 1;      // 2 warps along M (64 each)
    const int warp_n = wid >> 1;     // 4 warps along N (32 each)
    const int m0 = blockIdx.y * 128;
    const int n0 = blockIdx.x * 128;

    const uint32_t tb = (smem_u32(dynsm) + 127u) & ~127u;

    auto load_stage = [&](int stage, int kt) {
        const uint32_t sb = tb + stage * STAGE_BYTES;
        const int k0 = kt * 64;
        #pragma unroll
        for (int i = 0; i < 2; ++i) {            // A: 128 rows x 4 chunks of 16B
            const int u = tid + i * 256;
            const int row = u >> 2, c = u & 3;
            const uint32_t so = (uint32_t)(row * 64 + ((c ^ ((row >> 1) & 3)) << 4));
            const size_t ga = (size_t)(m0 + row) * lda + k0 + c * 16;
            cp_async16(sb + so,        aHi + ga);
            cp_async16(sb + 8192 + so, aLo + ga);
        }
        #pragma unroll
        for (int i = 0; i < 2; ++i) {            // B: 128 rows x 4 chunks of 16B
            const int u = tid + i * 256;
            const int row = u >> 2, c = u & 3;
            const uint32_t so = (uint32_t)(row * 64 + ((c ^ ((row >> 1) & 3)) << 4));
            const size_t gb = (size_t)(n0 + row) * ldb + k0 + c * 16;
            cp_async16(sb + 16384 + so, bHi + gb);
            cp_async16(sb + 24576 + so, bLo + gb);
        }
    };

    int ah[4][4][4], am[4][4][4];    // [m-tile][n8-tile][reg]: hh and mid accumulators
    #pragma unroll
    for (int i = 0; i < 4; ++i)
        #pragma unroll
        for (int j = 0; j < 4; ++j)
            #pragma unroll
            for (int q = 0; q < 4; ++q) { ah[i][j][q] = 0; am[i][j][q] = 0; }

    const int aRow = warp_m * 64 + (lane & 15);
    const int aSwz = (aRow >> 1) & 3;
    const int bRow = warp_n * 32 + (lane & 15);
    const int bSwz = (bRow >> 1) & 3;
    const int cHalf = lane >> 4;

    load_stage(0, 0); CP_COMMIT();
    load_stage(1, 1); CP_COMMIT();

    for (int kt = 0; kt < KT; ++kt) {
        CP_WAIT1();
        __syncthreads();
        if (kt + 2 < KT) load_stage((kt + 2) % 3, kt + 2);
        CP_COMMIT();

        const uint32_t sb = tb + (kt % 3) * STAGE_BYTES;
        #pragma unroll
        for (int ks = 0; ks < 2; ++ks) {         // two k32 steps per 64B ktile
            const int c = 2 * ks + cHalf;
            const uint32_t aco = (uint32_t)((c ^ aSwz) << 4);
            const uint32_t bco = (uint32_t)((c ^ bSwz) << 4);
            uint32_t fah[4][4], fal[4][4], fbh[2][4], fbl[2][4];
            #pragma unroll
            for (int mt = 0; mt < 4; ++mt) {
                ldsm_x4(fah[mt][0], fah[mt][1], fah[mt][2], fah[mt][3],
                        sb + (uint32_t)((aRow + mt * 16) * 64) + aco);
                ldsm_x4(fal[mt][0], fal[mt][1], fal[mt][2], fal[mt][3],
                        sb + 8192u + (uint32_t)((aRow + mt * 16) * 64) + aco);
            }
            #pragma unroll
            for (int i = 0; i < 2; ++i) {
                ldsm_x4(fbh[i][0], fbh[i][1], fbh[i][2], fbh[i][3],
                        sb + 16384u + (uint32_t)((bRow + i * 16) * 64) + bco);
                ldsm_x4(fbl[i][0], fbl[i][1], fbl[i][2], fbl[i][3],
                        sb + 24576u + (uint32_t)((bRow + i * 16) * 64) + bco);
            }
            #pragma unroll
            for (int mt = 0; mt < 4; ++mt) {
                #pragma unroll
                for (int n8 = 0; n8 < 4; ++n8) {
                    const int i = n8 >> 1, nl = n8 & 1;
                    // hh: Ahi x Bhi
                    mma_s8(ah[mt][n8][0], ah[mt][n8][1], ah[mt][n8][2], ah[mt][n8][3],
                           fah[mt][0], fah[mt][1], fah[mt][2], fah[mt][3],
                           fbh[i][nl], fbh[i][nl + 2]);
                    // mid: Ahi x Blo
                    mma_s8(am[mt][n8][0], am[mt][n8][1], am[mt][n8][2], am[mt][n8][3],
                           fah[mt][0], fah[mt][1], fah[mt][2], fah[mt][3],
                           fbl[i][nl], fbl[i][nl + 2]);
                    // mid: Alo x Bhi
                    mma_s8(am[mt][n8][0], am[mt][n8][1], am[mt][n8][2], am[mt][n8][3],
                           fal[mt][0], fal[mt][1], fal[mt][2], fal[mt][3],
                           fbh[i][nl], fbh[i][nl + 2]);
                }
            }
        }
    }

    // ------------- epilogue -------------
    const int colBase = n0 + warp_n * 32 + 2 * (lane & 3);
    const int rowBase = m0 + warp_m * 64 + (lane >> 2);
    if (EPI == 0) {
        #pragma unroll
        for (int n8 = 0; n8 < 4; ++n8) {
            const int col = colBase + n8 * 8;
            const float bv0 = __ldg(&bias[col]);
            const float bv1 = __ldg(&bias[col + 1]);
            #pragma unroll
            for (int mt = 0; mt < 4; ++mt) {
                const int r = rowBase + mt * 16;
                float2 v0, v1;
                v0.x = fmaf((float)ah[mt][n8][0], 65536.f, (float)am[mt][n8][0] * 256.f) * invS + bv0;
                v0.y = fmaf((float)ah[mt][n8][1], 65536.f, (float)am[mt][n8][1] * 256.f) * invS + bv1;
                v1.x = fmaf((float)ah[mt][n8][2], 65536.f, (float)am[mt][n8][2] * 256.f) * invS + bv0;
                v1.y = fmaf((float)ah[mt][n8][3], 65536.f, (float)am[mt][n8][3] * 256.f) * invS + bv1;
                *(float2*)(out + (size_t)r * ldo + col) = v0;
                *(float2*)(out + (size_t)(r + 8) * ldo + col) = v1;
            }
        }
    } else {
        #pragma unroll
        for (int n8 = 0; n8 < 4; ++n8) {
            #pragma unroll
            for (int j = 0; j < 2; ++j) {
                const int col = colBase + n8 * 8 + j;
                float m = -CUDART_INF_F;
                int curb = -1;
                #pragma unroll
                for (int mt = 0; mt < 4; ++mt) {
                    #pragma unroll
                    for (int half = 0; half < 2; ++half) {
                        const int r = rowBase + mt * 16 + half * 8;
                        const int bb = r / KSEL;
                        const float v = fmaf((float)ah[mt][n8][half * 2 + j], 65536.f,
                                             (float)am[mt][n8][half * 2 + j] * 256.f) * invS
                                        + partial[(size_t)r * ldo + col];
                        if (bb != curb) {
                            if (curb >= 0) atomicMaxFloat(&out[curb * EE + col], m);
                            curb = bb;
                            m = v;
                        } else {
                            m = fmaxf(m, v);
                        }
                    }
                }
                atomicMaxFloat(&out[curb * EE + col], m);
            }
        }
    }
}

// ---------------- BN stats / BN+ReLU+quant ------------------------------------
__global__ void stats_partial_kernel() {
    const int c4 = threadIdx.x;
    const int r0 = blockIdx.x * 32;
    float4 s = {0.f, 0.f, 0.f, 0.f}, q = {0.f, 0.f, 0.f, 0.f};
    #pragma unroll 4
    for (int r = 0; r < 32; ++r) {
        float4 v = *(const float4*)(g_h + (size_t)(r0 + r) * 512 + c4 * 4);
        s.x += v.x; s.y += v.y; s.z += v.z; s.w += v.w;
        q.x += v.x * v.x; q.y += v.y * v.y; q.z += v.z * v.z; q.w += v.w * v.w;
    }
    *(float4*)(g_psum + blockIdx.x * 512 + c4 * 4) = s;
    *(float4*)(g_psq  + blockIdx.x * 512 + c4 * 4) = q;
}
__global__ void stats_finalize_kernel(const float* __restrict__ gamma,
                                      const float* __restrict__ beta) {
    const int c = blockIdx.x * 128 + threadIdx.x;
    float s = 0.f, q = 0.f;
    for (int p = 0; p < NPART; ++p) {
        s += g_psum[p * 512 + c];
        q += g_psq [p * 512 + c];
    }
    const float invN = 1.0f / (float)MM;
    const float mean = s * invN;
    const float var  = q * invN - mean * mean;
    const float sc = gamma[c] * rsqrtf(var + 1e-5f);
    g_scale[c] = sc;
    g_shift[c] = beta[c] - mean * sc;
}
__global__ void bnrelu_quant_kernel() {
    const int idx = blockIdx.x * blockDim.x + threadIdx.x;   // MM*128 float4s
    const int n = idx >> 7, c4 = idx & 127;
    float4 v = *(const float4*)(g_h + (size_t)n * 512 + c4 * 4);
    const float4 sc = *(const float4*)(g_scale + c4 * 4);
    const float4 sh = *(const float4*)(g_shift + c4 * 4);
    int8_t hi[4], lo[4];
    quant16(fmaxf(fmaf(v.x, sc.x, sh.x), 0.f), S_AH, hi[0], lo[0]);
    quant16(fmaxf(fmaf(v.y, sc.y, sh.y), 0.f), S_AH, hi[1], lo[1]);
    quant16(fmaxf(fmaf(v.z, sc.z, sh.z), 0.f), S_AH, hi[2], lo[2]);
    quant16(fmaxf(fmaf(v.w, sc.w, sh.w), 0.f), S_AH, hi[3], lo[3]);
    const size_t off = (size_t)n * 512 + c4 * 4;
    *(uint32_t*)(g_hhi + off) = *(uint32_t*)hi;
    *(uint32_t*)(g_hlo + off) = *(uint32_t*)lo;
}

// ---------------- launch ------------------------------------------------------
extern "C" void kernel_launch(void* const* d_in, const int* in_sizes, int n_in,
                              void* d_out, int out_size) {
    const float* basef = (const float*)d_in[0];
    const float* atten = (const float*)d_in[1];
    const float* fc_w  = (const float*)d_in[2];
    const float* fc_b  = (const float*)d_in[3];
    const float* w0    = (const float*)d_in[4];
    const float* b0    = (const float*)d_in[5];
    const float* gamma = (const float*)d_in[6];
    const float* beta  = (const float*)d_in[7];
    const float* w1    = (const float*)d_in[8];
    const float* b1    = (const float*)d_in[9];
    float* out = (float*)d_out;

    cudaFuncSetAttribute(imma_gemm_kernel<0>, cudaFuncAttributeMaxDynamicSharedMemorySize, SMEM_DYN);
    cudaFuncSetAttribute(imma_gemm_kernel<2>, cudaFuncAttributeMaxDynamicSharedMemorySize, SMEM_DYN);

    void *pFhi, *pFlo, *pHhi, *pHlo, *pH, *pLocal, *pB2;
    void *pW0hi, *pW0lo, *pW1hi, *pW1lo, *pFChi, *pFClo;
    cudaGetSymbolAddress(&pFhi, g_fhi);
    cudaGetSymbolAddress(&pFlo, g_flo);
    cudaGetSymbolAddress(&pHhi, g_hhi);
    cudaGetSymbolAddress(&pHlo, g_hlo);
    cudaGetSymbolAddress(&pH, g_h);
    cudaGetSymbolAddress(&pLocal, g_local);
    cudaGetSymbolAddress(&pB2, g_bias2);
    cudaGetSymbolAddress(&pW0hi, g_w0hi);
    cudaGetSymbolAddress(&pW0lo, g_w0lo);
    cudaGetSymbolAddress(&pW1hi, g_w1hi);
    cudaGetSymbolAddress(&pW1lo, g_w1lo);
    cudaGetSymbolAddress(&pFChi, g_fchi);
    cudaGetSymbolAddress(&pFClo, g_fclo);

    const float inv_f = 1.0f / (S_AF * S_W);
    const float inv_h = 1.0f / (S_AH * S_W);

    // launch order: index 3 (ncu capture slot) = gemm1
    topk_kernel<<<NB, 256>>>(atten);                                      // 0
    gather_quant_kernel<<<dim3(KSEL, NB), 128>>>(basef);                  // 1
    quant_w_kernel<<<1024, 256>>>(w0, (int8_t*)pW0hi, (int8_t*)pW0lo, 512 * 512);  // 2

    // GEMM1: h = feats @ w0^T + b0   (M=MM, N=512, K=512 -> KT=8)
    imma_gemm_kernel<0><<<dim3(HH / 128, MM / 128), 256, SMEM_DYN>>>(     // 3
        (const int8_t*)pFhi, (const int8_t*)pFlo, 512,
        (const int8_t*)pW0hi, (const int8_t*)pW0lo, 512,
        b0, nullptr, inv_f, (float*)pH, 512, 8);

    quant_w_kernel<<<2048, 256>>>(w1, (int8_t*)pW1hi, (int8_t*)pW1lo, 1024 * 512);   // 4
    quant_w_kernel<<<2048, 256>>>(fc_w, (int8_t*)pFChi, (int8_t*)pFClo, 1024 * 512); // 5
    bias2_kernel<<<4, 256>>>(b1, fc_b);                                   // 6
    stats_partial_kernel<<<NPART, 128>>>();                               // 7
    stats_finalize_kernel<<<4, 128>>>(gamma, beta);                       // 8
    bnrelu_quant_kernel<<<(MM * 128) / 256, 256>>>();                     // 9
    init_out_kernel<<<(NB * EE + 255) / 256, 256>>>(out);                 // 10

    // GEMM2a: local = relu_bn_h @ w1^T + (b1 + fc_b)   (N=1024, K=512)
    imma_gemm_kernel<0><<<dim3(EE / 128, MM / 128), 256, SMEM_DYN>>>(     // 11
        (const int8_t*)pHhi, (const int8_t*)pHlo, 512,
        (const int8_t*)pW1hi, (const int8_t*)pW1lo, 512,
        (const float*)pB2, nullptr, inv_h, (float*)pLocal, 1024, 8);

    // GEMM2b: out = max_b( feats @ fc_w^T + local )    (fused max epilogue)
    imma_gemm_kernel<2><<<dim3(EE / 128, MM / 128), 256, SMEM_DYN>>>(     // 12
        (const int8_t*)pFhi, (const int8_t*)pFlo, 512,
        (const int8_t*)pFChi, (const int8_t*)pFClo, 512,
        nullptr, (const float*)pLocal, inv_f, out, 1024, 8);
}

// round 16
// speedup vs baseline: 2.5079x; 2.5079x over previous
#include <cuda_runtime.h>
#include <cuda_bf16.h>
#include <math_constants.h>
#include <cstdint>

#define NB   64
#define LL   577
#define DD   512
#define EE   1024
#define HH   512
#define KSEL 288
#define MM   (NB * KSEL)        // 18432 rows
#define NPART 144               // gemm1 M-blocks (each writes 512-col partial row)

// ---------------- scratch (static device globals; no allocation) -------------
__device__ __align__(16) __nv_bfloat16 g_Ahi[(size_t)MM * 1024]; // cols 0-511: relu_bn_h, 512-1023: feats
__device__ __align__(16) __nv_bfloat16 g_Alo[(size_t)MM * 1024];
__device__ __align__(16) float g_h[(size_t)MM * 512];
__device__ __align__(16) __nv_bfloat16 g_Whi[1024 * 1024];  // [e][k] k<512: w1, else fc_w
__device__ __align__(16) __nv_bfloat16 g_Wlo[1024 * 1024];
__device__ __align__(16) __nv_bfloat16 g_W0hi[512 * 512];
__device__ __align__(16) __nv_bfloat16 g_W0lo[512 * 512];
__device__ __align__(16) float g_bias2[1024];
__device__ __align__(16) float g_psum[NPART * 512];
__device__ __align__(16) float g_psq [NPART * 512];
__device__ __align__(16) float g_scale[512];
__device__ __align__(16) float g_shift[512];
__device__ int g_sel[NB * KSEL];

// ---------------- helpers ----------------------------------------------------
__device__ __forceinline__ uint32_t smem_u32(const void* p) {
    uint32_t a;
    asm("{ .reg .u64 t; cvta.to.shared.u64 t, %1; cvt.u32.u64 %0, t; }" : "=r"(a) : "l"(p));
    return a;
}
__device__ __forceinline__ void cp_async16(uint32_t saddr, const void* gaddr) {
    asm volatile("cp.async.cg.shared.global [%0], [%1], 16;" :: "r"(saddr), "l"(gaddr));
}
#define CP_COMMIT() asm volatile("cp.async.commit_group;" ::: "memory")
#define CP_WAIT1()  asm volatile("cp.async.wait_group 1;" ::: "memory")

__device__ __forceinline__ void ldsm_x4(uint32_t& r0, uint32_t& r1, uint32_t& r2, uint32_t& r3,
                                        uint32_t addr) {
    asm volatile("ldmatrix.sync.aligned.m8n8.x4.shared.b16 {%0,%1,%2,%3}, [%4];"
                 : "=r"(r0), "=r"(r1), "=r"(r2), "=r"(r3) : "r"(addr));
}
__device__ __forceinline__ void mma_bf16(float& d0, float& d1, float& d2, float& d3,
                                         uint32_t a0, uint32_t a1, uint32_t a2, uint32_t a3,
                                         uint32_t b0, uint32_t b1) {
    asm volatile("mma.sync.aligned.m16n8k16.row.col.f32.bf16.bf16.f32 "
                 "{%0,%1,%2,%3}, {%4,%5,%6,%7}, {%8,%9}, {%0,%1,%2,%3};"
                 : "+f"(d0), "+f"(d1), "+f"(d2), "+f"(d3)
                 : "r"(a0), "r"(a1), "r"(a2), "r"(a3), "r"(b0), "r"(b1));
}
__device__ __forceinline__ void atomicMaxFloat(float* addr, float val) {
    if (__float_as_int(val) >= 0) atomicMax((int*)addr, __float_as_int(val));
    else atomicMin((unsigned int*)addr, __float_as_uint(val));
}

// ---------------- small kernels ----------------------------------------------
__global__ void init_out_kernel(float* __restrict__ out) {
    int i = blockIdx.x * blockDim.x + threadIdx.x;
    if (i < NB * EE) out[i] = -CUDART_INF_F;
}

__global__ void topk_kernel(const float* __restrict__ atten) {
    __shared__ float s[LL];
    const int b = blockIdx.x;
    const float* __restrict__ row = atten + (size_t)b * LL * LL;
    for (int i = threadIdx.x; i < LL; i += blockDim.x)
        s[i] = (i == 0) ? -1.0f : row[i];
    __syncthreads();
    for (int i = threadIdx.x; i < LL; i += blockDim.x) {
        const float si = s[i];
        int rank = 0;
        #pragma unroll 4
        for (int j = 0; j < LL; ++j) {
            const float sj = s[j];
            rank += (sj > si) || (sj == si && j < i);
        }
        if (rank < KSEL) g_sel[b * KSEL + rank] = i;
    }
}

__global__ void gather_split_kernel(const float* __restrict__ basef) {
    const int t = blockIdx.x, b = blockIdx.y;
    const int n = b * KSEL + t;
    const int tok = g_sel[n];
    const float4* src = (const float4*)(basef + ((size_t)b * LL + tok) * DD);
    const float4 v = src[threadIdx.x];
    float ss = v.x * v.x + v.y * v.y + v.z * v.z + v.w * v.w;
    #pragma unroll
    for (int off = 16; off > 0; off >>= 1)
        ss += __shfl_xor_sync(0xffffffffu, ss, off);
    __shared__ float wsum[4];
    const int lane = threadIdx.x & 31, wid = threadIdx.x >> 5;
    if (lane == 0) wsum[wid] = ss;
    __syncthreads();
    const float tot = wsum[0] + wsum[1] + wsum[2] + wsum[3];
    const float inv = 1.0f / (sqrtf(tot) + 1e-8f);
    float f[4] = {v.x * inv, v.y * inv, v.z * inv, v.w * inv};
    __nv_bfloat16 hi[4], lo[4];
    #pragma unroll
    for (int i = 0; i < 4; ++i) {
        hi[i] = __float2bfloat16_rn(f[i]);
        lo[i] = __float2bfloat16_rn(f[i] - __bfloat162float(hi[i]));
    }
    const size_t off = (size_t)n * 1024 + 512 + threadIdx.x * 4;
    *(uint2*)(g_Ahi + off) = *(uint2*)hi;
    *(uint2*)(g_Alo + off) = *(uint2*)lo;
}

__global__ void split_w0_kernel(const float* __restrict__ w0) {
    const int i = blockIdx.x * blockDim.x + threadIdx.x;
    if (i >= 512 * 512) return;
    const float w = w0[i];
    const __nv_bfloat16 hi = __float2bfloat16_rn(w);
    g_W0hi[i] = hi;
    g_W0lo[i] = __float2bfloat16_rn(w - __bfloat162float(hi));
}
__global__ void split_wcat_kernel(const float* __restrict__ w1, const float* __restrict__ fcw) {
    const int i = blockIdx.x * blockDim.x + threadIdx.x;
    if (i >= 1024 * 1024) return;
    const int e = i >> 10, k = i & 1023;
    const float w = (k < 512) ? w1[e * 512 + k] : fcw[e * 512 + (k - 512)];
    const __nv_bfloat16 hi = __float2bfloat16_rn(w);
    g_Whi[i] = hi;
    g_Wlo[i] = __float2bfloat16_rn(w - __bfloat162float(hi));
}

// ---------------- HMMA GEMM (bf16 split, LDSM-minimized; R8 champion) ---------
// CTA tile 128x256, K-tile 32, 3-stage cp.async pipeline, 8 warps (2M x 4N),
// warp tile 64x64, bf16 3-pass split (hi*hi + lo*hi + hi*lo). 1 CTA/SM.
// EPI 0: out = acc + bias; ALSO reduces per-CTA column sum/sumsq of h into
//        deterministic partial slots g_psum/g_psq[by*512 + bx*256 + c]
//        (replaces the separate 38MB stats_partial pass).
// EPI 1: fused per-batch (KSEL rows) max via atomicMaxFloat into out (init -inf)
#define STAGE_BYTES 49152   // Ahi 8K | Alo 8K | Bhi 16K | Blo 16K
#define RED_BYTES   4096    // sred/qred: 2 arrays x 512 floats
#define SMEM_DYN (3 * STAGE_BYTES + RED_BYTES + 128)
extern __shared__ char dynsm[];

template<int EPI>
__global__ void __launch_bounds__(256, 1) hmma_gemm_kernel(
    const __nv_bfloat16* __restrict__ aHi, const __nv_bfloat16* __restrict__ aLo, int lda,
    const __nv_bfloat16* __restrict__ bHi, const __nv_bfloat16* __restrict__ bLo, int ldb,
    const float* __restrict__ bias, float* __restrict__ out, int ldo, int KT) {
    const int tid  = threadIdx.x;
    const int lane = tid & 31;
    const int wid  = tid >> 5;
    const int warp_m = wid & 1;      // 2 warps along M (64 each)
    const int warp_n = wid >> 1;     // 4 warps along N (64 each)
    const int m0 = blockIdx.y * 128;
    const int n0 = blockIdx.x * 256;

    const uint32_t smb = smem_u32(dynsm);
    const uint32_t tb = (smb + 127u) & ~127u;
    char* const redp = dynsm + (tb - smb) + 3 * STAGE_BYTES;  // 4KB reduction area

    auto load_stage = [&](int stage, int kt) {
        const uint32_t sb = tb + stage * STAGE_BYTES;
        const int k0 = kt * 32;
        #pragma unroll
        for (int i = 0; i < 2; ++i) {            // A: 128 rows x 4 chunks
            const int u = tid + i * 256;
            const int row = u >> 2, c = u & 3;
            const uint32_t so = (uint32_t)(row * 64 + ((c ^ ((row >> 1) & 3)) << 4));
            const size_t ga = (size_t)(m0 + row) * lda + k0 + c * 8;
            cp_async16(sb + so,        aHi + ga);
            cp_async16(sb + 8192 + so, aLo + ga);
        }
        #pragma unroll
        for (int i = 0; i < 4; ++i) {            // B: 256 rows x 4 chunks
            const int u = tid + i * 256;
            const int row = u >> 2, c = u & 3;
            const uint32_t so = (uint32_t)(row * 64 + ((c ^ ((row >> 1) & 3)) << 4));
            const size_t gb = (size_t)(n0 + row) * ldb + k0 + c * 8;
            cp_async16(sb + 16384 + so, bHi + gb);
            cp_async16(sb + 32768 + so, bLo + gb);
        }
    };

    float acc[4][8][4];
    #pragma unroll
    for (int i = 0; i < 4; ++i)
        #pragma unroll
        for (int j = 0; j < 8; ++j)
            #pragma unroll
            for (int q = 0; q < 4; ++q) acc[i][j][q] = 0.f;

    const int aRow = warp_m * 64 + (lane & 15);
    const int aSwz = (aRow >> 1) & 3;
    const int bRow = warp_n * 64 + (lane & 15);
    const int bSwz = (bRow >> 1) & 3;
    const int cHalf = lane >> 4;

    load_stage(0, 0); CP_COMMIT();
    load_stage(1, 1); CP_COMMIT();

    for (int kt = 0; kt < KT; ++kt) {
        CP_WAIT1();
        __syncthreads();
        if (kt + 2 < KT) load_stage((kt + 2) % 3, kt + 2);
        CP_COMMIT();

        const uint32_t sb = tb + (kt % 3) * STAGE_BYTES;
        #pragma unroll
        for (int ks = 0; ks < 2; ++ks) {
            const int c = 2 * ks + cHalf;
            const uint32_t aco = (uint32_t)((c ^ aSwz) << 4);
            const uint32_t bco = (uint32_t)((c ^ bSwz) << 4);
            uint32_t af[4][4], bf[4][4], al[4][4];
            #pragma unroll
            for (int mt = 0; mt < 4; ++mt)
                ldsm_x4(af[mt][0], af[mt][1], af[mt][2], af[mt][3],
                        sb + (uint32_t)((aRow + mt * 16) * 64) + aco);
            #pragma unroll
            for (int nt = 0; nt < 4; ++nt)
                ldsm_x4(bf[nt][0], bf[nt][1], bf[nt][2], bf[nt][3],
                        sb + 16384u + (uint32_t)((bRow + nt * 16) * 64) + bco);
            // pass 0: A_hi x B_hi
            #pragma unroll
            for (int mt = 0; mt < 4; ++mt)
                #pragma unroll
                for (int n8 = 0; n8 < 8; ++n8) {
                    const int nt = n8 >> 1, nl = n8 & 1;
                    mma_bf16(acc[mt][n8][0], acc[mt][n8][1], acc[mt][n8][2], acc[mt][n8][3],
                             af[mt][0], af[mt][1], af[mt][2], af[mt][3],
                             bf[nt][nl], bf[nt][nl + 2]);
                }
            // pass 1: A_lo x B_hi
            #pragma unroll
            for (int mt = 0; mt < 4; ++mt)
                ldsm_x4(al[mt][0], al[mt][1], al[mt][2], al[mt][3],
                        sb + 8192u + (uint32_t)((aRow + mt * 16) * 64) + aco);
            #pragma unroll
            for (int mt = 0; mt < 4; ++mt)
                #pragma unroll
                for (int n8 = 0; n8 < 8; ++n8) {
                    const int nt = n8 >> 1, nl = n8 & 1;
                    mma_bf16(acc[mt][n8][0], acc[mt][n8][1], acc[mt][n8][2], acc[mt][n8][3],
                             al[mt][0], al[mt][1], al[mt][2], al[mt][3],
                             bf[nt][nl], bf[nt][nl + 2]);
                }
            // pass 2: A_hi x B_lo (reuse bf registers)
            #pragma unroll
            for (int nt = 0; nt < 4; ++nt)
                ldsm_x4(bf[nt][0], bf[nt][1], bf[nt][2], bf[nt][3],
                        sb + 32768u + (uint32_t)((bRow + nt * 16) * 64) + bco);
            #pragma unroll
            for (int mt = 0; mt < 4; ++mt)
                #pragma unroll
                for (int n8 = 0; n8 < 8; ++n8) {
                    const int nt = n8 >> 1, nl = n8 & 1;
                    mma_bf16(acc[mt][n8][0], acc[mt][n8][1], acc[mt][n8][2], acc[mt][n8][3],
                             af[mt][0], af[mt][1], af[mt][2], af[mt][3],
                             bf[nt][nl], bf[nt][nl + 2]);
                }
        }
    }

    // ------------- epilogue -------------
    const int colBase = n0 + warp_n * 64 + 2 * (lane & 3);
    const int rowBase = m0 + warp_m * 64 + (lane >> 2);
    if (EPI == 0) {
        float s[16], q[16];
        #pragma unroll
        for (int i = 0; i < 16; ++i) { s[i] = 0.f; q[i] = 0.f; }
        #pragma unroll
        for (int n8 = 0; n8 < 8; ++n8) {
            const int col = colBase + n8 * 8;
            const float bv0 = __ldg(&bias[col]);
            const float bv1 = __ldg(&bias[col + 1]);
            #pragma unroll
            for (int mt = 0; mt < 4; ++mt) {
                const int r = rowBase + mt * 16;
                float2 v0 = {acc[mt][n8][0] + bv0, acc[mt][n8][1] + bv1};
                float2 v1 = {acc[mt][n8][2] + bv0, acc[mt][n8][3] + bv1};
                *(float2*)(out + (size_t)r * ldo + col) = v0;
                *(float2*)(out + (size_t)(r + 8) * ldo + col) = v1;
                s[n8 * 2 + 0] += v0.x + v1.x;
                s[n8 * 2 + 1] += v0.y + v1.y;
                q[n8 * 2 + 0] += v0.x * v0.x + v1.x * v1.x;
                q[n8 * 2 + 1] += v0.y * v0.y + v1.y * v1.y;
            }
        }
        // reduce across the 8 lanes sharing lane&3 (stride 4, 8, 16)
        #pragma unroll
        for (int i = 0; i < 16; ++i) {
            #pragma unroll
            for (int off = 4; off < 32; off <<= 1) {
                s[i] += __shfl_down_sync(0xffffffffu, s[i], off);
                q[i] += __shfl_down_sync(0xffffffffu, q[i], off);
            }
        }
        float* sred = (float*)redp;          // [2 wm][4 wn][4 l4][16]
        float* qred = sred + 512;
        __syncthreads();                      // all warps past mainloop smem use
        if ((lane >> 2) == 0) {
            const int base = (((warp_m * 4 + warp_n) * 4) + lane) * 16;
            #pragma unroll
            for (int i = 0; i < 16; ++i) { sred[base + i] = s[i]; qred[base + i] = q[i]; }
        }
        __syncthreads();
        if (tid < 256) {
            const int wn = tid >> 6, r = tid & 63;
            const int n8 = r >> 3, rr = r & 7, l4 = rr >> 1, j = rr & 1;
            const int k = n8 * 2 + j;
            const int i0 = ((0 * 4 + wn) * 4 + l4) * 16 + k;
            const int i1 = ((1 * 4 + wn) * 4 + l4) * 16 + k;
            const size_t slot = (size_t)blockIdx.y * 512 + blockIdx.x * 256 + tid;
            g_psum[slot] = sred[i0] + sred[i1];
            g_psq [slot] = qred[i0] + qred[i1];
        }
    } else {
        #pragma unroll
        for (int n8 = 0; n8 < 8; ++n8) {
            #pragma unroll
            for (int j = 0; j < 2; ++j) {
                const int col = colBase + n8 * 8 + j;
                const float bv = __ldg(&bias[col]);
                float m = -CUDART_INF_F;
                int curb = -1;
                #pragma unroll
                for (int mt = 0; mt < 4; ++mt) {
                    #pragma unroll
                    for (int half = 0; half < 2; ++half) {
                        const int r = rowBase + mt * 16 + half * 8;
                        const int bb = r / KSEL;
                        const float v = acc[mt][n8][half * 2 + j] + bv;
                        if (bb != curb) {
                            if (curb >= 0) atomicMaxFloat(&out[curb * EE + col], m);
                            curb = bb;
                            m = v;
                        } else {
                            m = fmaxf(m, v);
                        }
                    }
                }
                atomicMaxFloat(&out[curb * EE + col], m);
            }
        }
    }
}

// ---------------- finalize: BN scale/shift (144 partials) + bias2 -------------
__global__ void finalize_kernel(const float* __restrict__ gamma,
                                const float* __restrict__ beta,
                                const float* __restrict__ b1,
                                const float* __restrict__ bfc) {
    const int c = blockIdx.x * 256 + threadIdx.x;   // grid 4 x 256 = 1024
    g_bias2[c] = b1[c] + bfc[c];
    if (c < 512) {
        float s = 0.f, q = 0.f;
        for (int p = 0; p < NPART; ++p) {
            s += g_psum[p * 512 + c];
            q += g_psq [p * 512 + c];
        }
        const float invN = 1.0f / (float)MM;
        const float mean = s * invN;
        const float var  = q * invN - mean * mean;
        const float sc = gamma[c] * rsqrtf(var + 1e-5f);
        g_scale[c] = sc;
        g_shift[c] = beta[c] - mean * sc;
    }
}

__global__ void bnrelu_split_kernel() {
    const int idx = blockIdx.x * blockDim.x + threadIdx.x;
    const int n = idx >> 7, c4 = idx & 127;
    float4 v = *(const float4*)(g_h + (size_t)n * 512 + c4 * 4);
    const float4 sc = *(const float4*)(g_scale + c4 * 4);
    const float4 sh = *(const float4*)(g_shift + c4 * 4);
    float y[4];
    y[0] = fmaxf(fmaf(v.x, sc.x, sh.x), 0.f);
    y[1] = fmaxf(fmaf(v.y, sc.y, sh.y), 0.f);
    y[2] = fmaxf(fmaf(v.z, sc.z, sh.z), 0.f);
    y[3] = fmaxf(fmaf(v.w, sc.w, sh.w), 0.f);
    __nv_bfloat16 hi[4], lo[4];
    #pragma unroll
    for (int i = 0; i < 4; ++i) {
        hi[i] = __float2bfloat16_rn(y[i]);
        lo[i] = __float2bfloat16_rn(y[i] - __bfloat162float(hi[i]));
    }
    const size_t off = (size_t)n * 1024 + c4 * 4;
    *(uint2*)(g_Ahi + off) = *(uint2*)hi;
    *(uint2*)(g_Alo + off) = *(uint2*)lo;
}

// ---------------- launch ------------------------------------------------------
extern "C" void kernel_launch(void* const* d_in, const int* in_sizes, int n_in,
                              void* d_out, int out_size) {
    const float* basef = (const float*)d_in[0];
    const float* atten = (const float*)d_in[1];
    const float* fc_w  = (const float*)d_in[2];
    const float* fc_b  = (const float*)d_in[3];
    const float* w0    = (const float*)d_in[4];
    const float* b0    = (const float*)d_in[5];
    const float* gamma = (const float*)d_in[6];
    const float* beta  = (const float*)d_in[7];
    const float* w1    = (const float*)d_in[8];
    const float* b1    = (const float*)d_in[9];
    float* out = (float*)d_out;

    cudaFuncSetAttribute(hmma_gemm_kernel<0>, cudaFuncAttributeMaxDynamicSharedMemorySize, SMEM_DYN);
    cudaFuncSetAttribute(hmma_gemm_kernel<1>, cudaFuncAttributeMaxDynamicSharedMemorySize, SMEM_DYN);

    void *pAhi, *pAlo, *pW0hi, *pW0lo, *pWhi, *pWlo, *pB2, *pH;
    cudaGetSymbolAddress(&pAhi, g_Ahi);
    cudaGetSymbolAddress(&pAlo, g_Alo);
    cudaGetSymbolAddress(&pW0hi, g_W0hi);
    cudaGetSymbolAddress(&pW0lo, g_W0lo);
    cudaGetSymbolAddress(&pWhi, g_Whi);
    cudaGetSymbolAddress(&pWlo, g_Wlo);
    cudaGetSymbolAddress(&pB2, g_bias2);
    cudaGetSymbolAddress(&pH, g_h);

    // launch order: index 3 (ncu capture slot) = gemm1
    topk_kernel<<<NB, 256>>>(atten);                       // 0
    gather_split_kernel<<<dim3(KSEL, NB), 128>>>(basef);   // 1
    split_w0_kernel<<<1024, 256>>>(w0);                    // 2

    // GEMM1: h = feats @ w0^T + b0 (+ fused per-CTA BN partial stats)
    hmma_gemm_kernel<0><<<dim3(HH / 256, MM / 128), 256, SMEM_DYN>>>(   // 3
        (const __nv_bfloat16*)pAhi + 512, (const __nv_bfloat16*)pAlo + 512, 1024,
        (const __nv_bfloat16*)pW0hi, (const __nv_bfloat16*)pW0lo, 512,
        b0, (float*)pH, 512, 16);

    split_wcat_kernel<<<4096, 256>>>(w1, fc_w);            // 4
    finalize_kernel<<<4, 256>>>(gamma, beta, b1, fc_b);    // 5 (stats + bias2)
    bnrelu_split_kernel<<<(MM * 128) / 256, 256>>>();      // 6
    init_out_kernel<<<(NB * EE + 255) / 256, 256>>>(out);  // 7

    // GEMM2: fused max of [relu_bn_h | feats] @ [w1 | fc_w]^T + (b1+fc_b)
    hmma_gemm_kernel<1><<<dim3(EE / 256, MM / 128), 256, SMEM_DYN>>>(   // 8
        (const __nv_bfloat16*)pAhi, (const __nv_bfloat16*)pAlo, 1024,
        (const __nv_bfloat16*)pWhi, (const __nv_bfloat16*)pWlo, 1024,
        (const float*)pB2, out, EE, 32);
}

// round 17
// speedup vs baseline: 2.5510x; 1.0172x over previous
#include <cuda_runtime.h>
#include <cuda_bf16.h>
#include <math_constants.h>
#include <cstdint>

#define NB   64
#define LL   577
#define DD   512
#define EE   1024
#define HH   512
#define KSEL 288
#define MM   (NB * KSEL)        // 18432 rows
#define NPART 144               // gemm1 M-blocks (each writes 512-col partial row)

// ---------------- scratch (static device globals; no allocation) -------------
__device__ __align__(16) __nv_bfloat16 g_Ahi[(size_t)MM * 1024]; // cols 0-511: relu_bn_h, 512-1023: feats
__device__ __align__(16) __nv_bfloat16 g_Alo[(size_t)MM * 1024];
__device__ __align__(16) float g_h[(size_t)MM * 512];
__device__ __align__(16) __nv_bfloat16 g_Whi[1024 * 1024];  // [e][k] k<512: w1, else fc_w
__device__ __align__(16) __nv_bfloat16 g_Wlo[1024 * 1024];
__device__ __align__(16) __nv_bfloat16 g_W0hi[512 * 512];
__device__ __align__(16) __nv_bfloat16 g_W0lo[512 * 512];
__device__ __align__(16) float g_bias2[1024];
__device__ __align__(16) float g_psum[NPART * 512];
__device__ __align__(16) float g_psq [NPART * 512];
__device__ __align__(16) float g_scale[512];
__device__ __align__(16) float g_shift[512];
__device__ int g_sel[NB * KSEL];

// ---------------- helpers ----------------------------------------------------
__device__ __forceinline__ uint32_t smem_u32(const void* p) {
    uint32_t a;
    asm("{ .reg .u64 t; cvta.to.shared.u64 t, %1; cvt.u32.u64 %0, t; }" : "=r"(a) : "l"(p));
    return a;
}
__device__ __forceinline__ void cp_async16(uint32_t saddr, const void* gaddr) {
    asm volatile("cp.async.cg.shared.global [%0], [%1], 16;" :: "r"(saddr), "l"(gaddr));
}
#define CP_COMMIT() asm volatile("cp.async.commit_group;" ::: "memory")
#define CP_WAIT1()  asm volatile("cp.async.wait_group 1;" ::: "memory")

__device__ __forceinline__ void ldsm_x4(uint32_t& r0, uint32_t& r1, uint32_t& r2, uint32_t& r3,
                                        uint32_t addr) {
    asm volatile("ldmatrix.sync.aligned.m8n8.x4.shared.b16 {%0,%1,%2,%3}, [%4];"
                 : "=r"(r0), "=r"(r1), "=r"(r2), "=r"(r3) : "r"(addr));
}
__device__ __forceinline__ void mma_bf16(float& d0, float& d1, float& d2, float& d3,
                                         uint32_t a0, uint32_t a1, uint32_t a2, uint32_t a3,
                                         uint32_t b0, uint32_t b1) {
    asm volatile("mma.sync.aligned.m16n8k16.row.col.f32.bf16.bf16.f32 "
                 "{%0,%1,%2,%3}, {%4,%5,%6,%7}, {%8,%9}, {%0,%1,%2,%3};"
                 : "+f"(d0), "+f"(d1), "+f"(d2), "+f"(d3)
                 : "r"(a0), "r"(a1), "r"(a2), "r"(a3), "r"(b0), "r"(b1));
}
__device__ __forceinline__ void atomicMaxFloat(float* addr, float val) {
    if (__float_as_int(val) >= 0) atomicMax((int*)addr, __float_as_int(val));
    else atomicMin((unsigned int*)addr, __float_as_uint(val));
}
__device__ __forceinline__ void split4(const float4 w, uint2& hi, uint2& lo) {
    __nv_bfloat16 h[4], l[4];
    const float f[4] = {w.x, w.y, w.z, w.w};
    #pragma unroll
    for (int i = 0; i < 4; ++i) {
        h[i] = __float2bfloat16_rn(f[i]);
        l[i] = __float2bfloat16_rn(f[i] - __bfloat162float(h[i]));
    }
    hi = *(uint2*)h;
    lo = *(uint2*)l;
}

// ---------------- small kernels ----------------------------------------------
__global__ void topk_kernel(const float* __restrict__ atten) {
    __shared__ float s[LL];
    const int b = blockIdx.x;
    const float* __restrict__ row = atten + (size_t)b * LL * LL;
    for (int i = threadIdx.x; i < LL; i += blockDim.x)
        s[i] = (i == 0) ? -1.0f : row[i];
    __syncthreads();
    for (int i = threadIdx.x; i < LL; i += blockDim.x) {
        const float si = s[i];
        int rank = 0;
        #pragma unroll 4
        for (int j = 0; j < LL; ++j) {
            const float sj = s[j];
            rank += (sj > si) || (sj == si && j < i);
        }
        if (rank < KSEL) g_sel[b * KSEL + rank] = i;
    }
}

// warp-per-token gather + L2-norm + bf16 split (8 tokens per 256-thread CTA)
__global__ void gather_split_kernel(const float* __restrict__ basef) {
    const int wrp  = threadIdx.x >> 5;
    const int lane = threadIdx.x & 31;
    const int n = blockIdx.x * 8 + wrp;            // token row in [0, MM)
    const int b = n / KSEL;
    const int tok = g_sel[n];
    const float4* src = (const float4*)(basef + ((size_t)b * LL + tok) * DD);
    float4 v[4];
    float ss = 0.f;
    #pragma unroll
    for (int i = 0; i < 4; ++i) {
        v[i] = src[lane + 32 * i];
        ss += v[i].x * v[i].x + v[i].y * v[i].y + v[i].z * v[i].z + v[i].w * v[i].w;
    }
    #pragma unroll
    for (int off = 16; off > 0; off >>= 1)
        ss += __shfl_xor_sync(0xffffffffu, ss, off);
    const float inv = 1.0f / (sqrtf(ss) + 1e-8f);
    #pragma unroll
    for (int i = 0; i < 4; ++i) {
        float4 f = {v[i].x * inv, v[i].y * inv, v[i].z * inv, v[i].w * inv};
        uint2 hi, lo;
        split4(f, hi, lo);
        const size_t off2 = (size_t)n * 1024 + 512 + (lane + 32 * i) * 4;
        *(uint2*)(g_Ahi + off2) = hi;
        *(uint2*)(g_Alo + off2) = lo;
    }
}

// one kernel: split w0 (65536 float4s) + concat-split [w1 | fc_w] (262144 float4s)
#define NW0_F4 65536
#define NWC_F4 262144
__global__ void prep_w_kernel(const float* __restrict__ w0, const float* __restrict__ w1,
                              const float* __restrict__ fcw) {
    const int idx = blockIdx.x * blockDim.x + threadIdx.x;
    if (idx < NW0_F4) {
        const float4 w = ((const float4*)w0)[idx];
        uint2 hi, lo;
        split4(w, hi, lo);
        *(uint2*)(g_W0hi + idx * 4) = hi;
        *(uint2*)(g_W0lo + idx * 4) = lo;
    } else if (idx < NW0_F4 + NWC_F4) {
        const int i4 = (idx - NW0_F4) * 4;
        const int e = i4 >> 10, k = i4 & 1023;     // k multiple of 4, half-aligned
        const float4 w = (k < 512)
            ? *(const float4*)(w1 + (size_t)e * 512 + k)
            : *(const float4*)(fcw + (size_t)e * 512 + (k - 512));
        uint2 hi, lo;
        split4(w, hi, lo);
        *(uint2*)(g_Whi + i4) = hi;
        *(uint2*)(g_Wlo + i4) = lo;
    }
}

// ---------------- HMMA GEMM (bf16 split, LDSM-minimized; R8/R16 champion) -----
// CTA tile 128x256, K-tile 32, 3-stage cp.async pipeline, 8 warps (2M x 4N),
// warp tile 64x64, bf16 3-pass split (hi*hi + lo*hi + hi*lo). 1 CTA/SM.
// EPI 0: out = acc + bias; ALSO reduces per-CTA column sum/sumsq of h into
//        deterministic partial slots g_psum/g_psq[by*512 + bx*256 + c].
// EPI 1: fused per-batch (KSEL rows) max via atomicMaxFloat into out (init -inf)
#define STAGE_BYTES 49152   // Ahi 8K | Alo 8K | Bhi 16K | Blo 16K
#define RED_BYTES   4096    // sred/qred: 2 arrays x 512 floats
#define SMEM_DYN (3 * STAGE_BYTES + RED_BYTES + 128)
extern __shared__ char dynsm[];

template<int EPI>
__global__ void __launch_bounds__(256, 1) hmma_gemm_kernel(
    const __nv_bfloat16* __restrict__ aHi, const __nv_bfloat16* __restrict__ aLo, int lda,
    const __nv_bfloat16* __restrict__ bHi, const __nv_bfloat16* __restrict__ bLo, int ldb,
    const float* __restrict__ bias, float* __restrict__ out, int ldo, int KT) {
    const int tid  = threadIdx.x;
    const int lane = tid & 31;
    const int wid  = tid >> 5;
    const int warp_m = wid & 1;      // 2 warps along M (64 each)
    const int warp_n = wid >> 1;     // 4 warps along N (64 each)
    const int m0 = blockIdx.y * 128;
    const int n0 = blockIdx.x * 256;

    const uint32_t smb = smem_u32(dynsm);
    const uint32_t tb = (smb + 127u) & ~127u;
    char* const redp = dynsm + (tb - smb) + 3 * STAGE_BYTES;  // 4KB reduction area

    auto load_stage = [&](int stage, int kt) {
        const uint32_t sb = tb + stage * STAGE_BYTES;
        const int k0 = kt * 32;
        #pragma unroll
        for (int i = 0; i < 2; ++i) {            // A: 128 rows x 4 chunks
            const int u = tid + i * 256;
            const int row = u >> 2, c = u & 3;
            const uint32_t so = (uint32_t)(row * 64 + ((c ^ ((row >> 1) & 3)) << 4));
            const size_t ga = (size_t)(m0 + row) * lda + k0 + c * 8;
            cp_async16(sb + so,        aHi + ga);
            cp_async16(sb + 8192 + so, aLo + ga);
        }
        #pragma unroll
        for (int i = 0; i < 4; ++i) {            // B: 256 rows x 4 chunks
            const int u = tid + i * 256;
            const int row = u >> 2, c = u & 3;
            const uint32_t so = (uint32_t)(row * 64 + ((c ^ ((row >> 1) & 3)) << 4));
            const size_t gb = (size_t)(n0 + row) * ldb + k0 + c * 8;
            cp_async16(sb + 16384 + so, bHi + gb);
            cp_async16(sb + 32768 + so, bLo + gb);
        }
    };

    float acc[4][8][4];
    #pragma unroll
    for (int i = 0; i < 4; ++i)
        #pragma unroll
        for (int j = 0; j < 8; ++j)
            #pragma unroll
            for (int q = 0; q < 4; ++q) acc[i][j][q] = 0.f;

    const int aRow = warp_m * 64 + (lane & 15);
    const int aSwz = (aRow >> 1) & 3;
    const int bRow = warp_n * 64 + (lane & 15);
    const int bSwz = (bRow >> 1) & 3;
    const int cHalf = lane >> 4;

    load_stage(0, 0); CP_COMMIT();
    load_stage(1, 1); CP_COMMIT();

    for (int kt = 0; kt < KT; ++kt) {
        CP_WAIT1();
        __syncthreads();
        if (kt + 2 < KT) load_stage((kt + 2) % 3, kt + 2);
        CP_COMMIT();

        const uint32_t sb = tb + (kt % 3) * STAGE_BYTES;
        #pragma unroll
        for (int ks = 0; ks < 2; ++ks) {
            const int c = 2 * ks + cHalf;
            const uint32_t aco = (uint32_t)((c ^ aSwz) << 4);
            const uint32_t bco = (uint32_t)((c ^ bSwz) << 4);
            uint32_t af[4][4], bf[4][4], al[4][4];
            #pragma unroll
            for (int mt = 0; mt < 4; ++mt)
                ldsm_x4(af[mt][0], af[mt][1], af[mt][2], af[mt][3],
                        sb + (uint32_t)((aRow + mt * 16) * 64) + aco);
            #pragma unroll
            for (int nt = 0; nt < 4; ++nt)
                ldsm_x4(bf[nt][0], bf[nt][1], bf[nt][2], bf[nt][3],
                        sb + 16384u + (uint32_t)((bRow + nt * 16) * 64) + bco);
            // pass 0: A_hi x B_hi
            #pragma unroll
            for (int mt = 0; mt < 4; ++mt)
                #pragma unroll
                for (int n8 = 0; n8 < 8; ++n8) {
                    const int nt = n8 >> 1, nl = n8 & 1;
                    mma_bf16(acc[mt][n8][0], acc[mt][n8][1], acc[mt][n8][2], acc[mt][n8][3],
                             af[mt][0], af[mt][1], af[mt][2], af[mt][3],
                             bf[nt][nl], bf[nt][nl + 2]);
                }
            // pass 1: A_lo x B_hi
            #pragma unroll
            for (int mt = 0; mt < 4; ++mt)
                ldsm_x4(al[mt][0], al[mt][1], al[mt][2], al[mt][3],
                        sb + 8192u + (uint32_t)((aRow + mt * 16) * 64) + aco);
            #pragma unroll
            for (int mt = 0; mt < 4; ++mt)
                #pragma unroll
                for (int n8 = 0; n8 < 8; ++n8) {
                    const int nt = n8 >> 1, nl = n8 & 1;
                    mma_bf16(acc[mt][n8][0], acc[mt][n8][1], acc[mt][n8][2], acc[mt][n8][3],
                             al[mt][0], al[mt][1], al[mt][2], al[mt][3],
                             bf[nt][nl], bf[nt][nl + 2]);
                }
            // pass 2: A_hi x B_lo (reuse bf registers)
            #pragma unroll
            for (int nt = 0; nt < 4; ++nt)
                ldsm_x4(bf[nt][0], bf[nt][1], bf[nt][2], bf[nt][3],
                        sb + 32768u + (uint32_t)((bRow + nt * 16) * 64) + bco);
            #pragma unroll
            for (int mt = 0; mt < 4; ++mt)
                #pragma unroll
                for (int n8 = 0; n8 < 8; ++n8) {
                    const int nt = n8 >> 1, nl = n8 & 1;
                    mma_bf16(acc[mt][n8][0], acc[mt][n8][1], acc[mt][n8][2], acc[mt][n8][3],
                             af[mt][0], af[mt][1], af[mt][2], af[mt][3],
                             bf[nt][nl], bf[nt][nl + 2]);
                }
        }
    }

    // ------------- epilogue -------------
    const int colBase = n0 + warp_n * 64 + 2 * (lane & 3);
    const int rowBase = m0 + warp_m * 64 + (lane >> 2);
    if (EPI == 0) {
        float s[16], q[16];
        #pragma unroll
        for (int i = 0; i < 16; ++i) { s[i] = 0.f; q[i] = 0.f; }
        #pragma unroll
        for (int n8 = 0; n8 < 8; ++n8) {
            const int col = colBase + n8 * 8;
            const float bv0 = __ldg(&bias[col]);
            const float bv1 = __ldg(&bias[col + 1]);
            #pragma unroll
            for (int mt = 0; mt < 4; ++mt) {
                const int r = rowBase + mt * 16;
                float2 v0 = {acc[mt][n8][0] + bv0, acc[mt][n8][1] + bv1};
                float2 v1 = {acc[mt][n8][2] + bv0, acc[mt][n8][3] + bv1};
                *(float2*)(out + (size_t)r * ldo + col) = v0;
                *(float2*)(out + (size_t)(r + 8) * ldo + col) = v1;
                s[n8 * 2 + 0] += v0.x + v1.x;
                s[n8 * 2 + 1] += v0.y + v1.y;
                q[n8 * 2 + 0] += v0.x * v0.x + v1.x * v1.x;
                q[n8 * 2 + 1] += v0.y * v0.y + v1.y * v1.y;
            }
        }
        #pragma unroll
        for (int i = 0; i < 16; ++i) {
            #pragma unroll
            for (int off = 4; off < 32; off <<= 1) {
                s[i] += __shfl_down_sync(0xffffffffu, s[i], off);
                q[i] += __shfl_down_sync(0xffffffffu, q[i], off);
            }
        }
        float* sred = (float*)redp;          // [2 wm][4 wn][4 l4][16]
        float* qred = sred + 512;
        __syncthreads();
        if ((lane >> 2) == 0) {
            const int base = (((warp_m * 4 + warp_n) * 4) + lane) * 16;
            #pragma unroll
            for (int i = 0; i < 16; ++i) { sred[base + i] = s[i]; qred[base + i] = q[i]; }
        }
        __syncthreads();
        if (tid < 256) {
            const int wn = tid >> 6, r = tid & 63;
            const int n8 = r >> 3, rr = r & 7, l4 = rr >> 1, j = rr & 1;
            const int k = n8 * 2 + j;
            const int i0 = ((0 * 4 + wn) * 4 + l4) * 16 + k;
            const int i1 = ((1 * 4 + wn) * 4 + l4) * 16 + k;
            const size_t slot = (size_t)blockIdx.y * 512 + blockIdx.x * 256 + tid;
            g_psum[slot] = sred[i0] + sred[i1];
            g_psq [slot] = qred[i0] + qred[i1];
        }
    } else {
        #pragma unroll
        for (int n8 = 0; n8 < 8; ++n8) {
            #pragma unroll
            for (int j = 0; j < 2; ++j) {
                const int col = colBase + n8 * 8 + j;
                const float bv = __ldg(&bias[col]);
                float m = -CUDART_INF_F;
                int curb = -1;
                #pragma unroll
                for (int mt = 0; mt < 4; ++mt) {
                    #pragma unroll
                    for (int half = 0; half < 2; ++half) {
                        const int r = rowBase + mt * 16 + half * 8;
                        const int bb = r / KSEL;
                        const float v = acc[mt][n8][half * 2 + j] + bv;
                        if (bb != curb) {
                            if (curb >= 0) atomicMaxFloat(&out[curb * EE + col], m);
                            curb = bb;
                            m = v;
                        } else {
                            m = fmaxf(m, v);
                        }
                    }
                }
                atomicMaxFloat(&out[curb * EE + col], m);
            }
        }
    }
}

// ---------------- finalize: out=-inf init + bias2 + BN scale/shift ------------
__global__ void finalize_init_kernel(const float* __restrict__ gamma,
                                     const float* __restrict__ beta,
                                     const float* __restrict__ b1,
                                     const float* __restrict__ bfc,
                                     float* __restrict__ out) {
    const int g = blockIdx.x * 256 + threadIdx.x;   // grid 256 x 256 = 65536
    out[g] = -CUDART_INF_F;                         // NB*EE == 65536 exactly
    if (g < 1024) g_bias2[g] = b1[g] + bfc[g];
    if (g < 512) {
        float s = 0.f, q = 0.f;
        for (int p = 0; p < NPART; ++p) {
            s += g_psum[p * 512 + g];
            q += g_psq [p * 512 + g];
        }
        const float invN = 1.0f / (float)MM;
        const float mean = s * invN;
        const float var  = q * invN - mean * mean;
        const float sc = gamma[g] * rsqrtf(var + 1e-5f);
        g_scale[g] = sc;
        g_shift[g] = beta[g] - mean * sc;
    }
}

__global__ void bnrelu_split_kernel() {
    const int idx = blockIdx.x * blockDim.x + threadIdx.x;
    const int n = idx >> 7, c4 = idx & 127;
    float4 v = *(const float4*)(g_h + (size_t)n * 512 + c4 * 4);
    const float4 sc = *(const float4*)(g_scale + c4 * 4);
    const float4 sh = *(const float4*)(g_shift + c4 * 4);
    float4 y;
    y.x = fmaxf(fmaf(v.x, sc.x, sh.x), 0.f);
    y.y = fmaxf(fmaf(v.y, sc.y, sh.y), 0.f);
    y.z = fmaxf(fmaf(v.z, sc.z, sh.z), 0.f);
    y.w = fmaxf(fmaf(v.w, sc.w, sh.w), 0.f);
    uint2 hi, lo;
    split4(y, hi, lo);
    const size_t off = (size_t)n * 1024 + c4 * 4;
    *(uint2*)(g_Ahi + off) = hi;
    *(uint2*)(g_Alo + off) = lo;
}

// ---------------- launch ------------------------------------------------------
extern "C" void kernel_launch(void* const* d_in, const int* in_sizes, int n_in,
                              void* d_out, int out_size) {
    const float* basef = (const float*)d_in[0];
    const float* atten = (const float*)d_in[1];
    const float* fc_w  = (const float*)d_in[2];
    const float* fc_b  = (const float*)d_in[3];
    const float* w0    = (const float*)d_in[4];
    const float* b0    = (const float*)d_in[5];
    const float* gamma = (const float*)d_in[6];
    const float* beta  = (const float*)d_in[7];
    const float* w1    = (const float*)d_in[8];
    const float* b1    = (const float*)d_in[9];
    float* out = (float*)d_out;

    cudaFuncSetAttribute(hmma_gemm_kernel<0>, cudaFuncAttributeMaxDynamicSharedMemorySize, SMEM_DYN);
    cudaFuncSetAttribute(hmma_gemm_kernel<1>, cudaFuncAttributeMaxDynamicSharedMemorySize, SMEM_DYN);

    void *pAhi, *pAlo, *pW0hi, *pW0lo, *pWhi, *pWlo, *pB2, *pH;
    cudaGetSymbolAddress(&pAhi, g_Ahi);
    cudaGetSymbolAddress(&pAlo, g_Alo);
    cudaGetSymbolAddress(&pW0hi, g_W0hi);
    cudaGetSymbolAddress(&pW0lo, g_W0lo);
    cudaGetSymbolAddress(&pWhi, g_Whi);
    cudaGetSymbolAddress(&pWlo, g_Wlo);
    cudaGetSymbolAddress(&pB2, g_bias2);
    cudaGetSymbolAddress(&pH, g_h);

    // launch order: index 3 (ncu capture slot) = gemm1
    topk_kernel<<<NB, 256>>>(atten);                       // 0
    gather_split_kernel<<<MM / 8, 256>>>(basef);           // 1
    prep_w_kernel<<<(NW0_F4 + NWC_F4) / 256, 256>>>(w0, w1, fc_w);  // 2

    // GEMM1: h = feats @ w0^T + b0 (+ fused per-CTA BN partial stats)
    hmma_gemm_kernel<0><<<dim3(HH / 256, MM / 128), 256, SMEM_DYN>>>(   // 3
        (const __nv_bfloat16*)pAhi + 512, (const __nv_bfloat16*)pAlo + 512, 1024,
        (const __nv_bfloat16*)pW0hi, (const __nv_bfloat16*)pW0lo, 512,
        b0, (float*)pH, 512, 16);

    finalize_init_kernel<<<256, 256>>>(gamma, beta, b1, fc_b, out);  // 4
    bnrelu_split_kernel<<<(MM * 128) / 256, 256>>>();                // 5

    // GEMM2: fused max of [relu_bn_h | feats] @ [w1 | fc_w]^T + (b1+fc_b)
    hmma_gemm_kernel<1><<<dim3(EE / 256, MM / 128), 256, SMEM_DYN>>>(   // 6
        (const __nv_bfloat16*)pAhi, (const __nv_bfloat16*)pAlo, 1024,
        (const __nv_bfloat16*)pWhi, (const __nv_bfloat16*)pWlo, 1024,
        (const float*)pB2, out, EE, 32);
}